// round 3
// baseline (speedup 1.0000x reference)
#include <cuda_runtime.h>

#define NT 8192
#define THRESH 0.7f

// Scratch (device globals: allocation-free rule)
__device__ float g_Mt[64 * NT];   // Mt[f][i] = (U@W)[i][f]
__device__ float g_Ut[64 * NT];   // Ut[f][j] = U[j][f]
__device__ float g_V [NT * 128];  // V[i][b*64+d] = relu(prof[b,i]-thr) * state[b,i,d]

// ---------- packed f32x2 helpers ----------
__device__ __forceinline__ unsigned long long ffma2(unsigned long long a,
                                                    unsigned long long b,
                                                    unsigned long long c) {
    unsigned long long d;
    asm("fma.rn.f32x2 %0, %1, %2, %3;" : "=l"(d) : "l"(a), "l"(b), "l"(c));
    return d;
}
__device__ __forceinline__ unsigned long long addf2(unsigned long long a,
                                                    unsigned long long b) {
    unsigned long long d;
    asm("add.rn.f32x2 %0, %1, %2;" : "=l"(d) : "l"(a), "l"(b));
    return d;
}
__device__ __forceinline__ unsigned long long dup2(float x) {
    unsigned long long d; unsigned int xi = __float_as_uint(x);
    asm("mov.b64 %0, {%1, %2};" : "=l"(d) : "r"(xi), "r"(xi));
    return d;
}
__device__ __forceinline__ float sigmoidf_fast(float x) {
    return __fdividef(1.f, 1.f + __expf(-x));
}

// ---------- prep: Mt = (U@W)^T (f-major), Ut = U^T ----------
__global__ void prep_mu_kernel(const float* __restrict__ U,
                               const float* __restrict__ W) {
    __shared__ float ws[64 * 64];
    __shared__ float us[64 * 64];
    const int tid = threadIdx.x;
    const int i0  = blockIdx.x * 64;
    #pragma unroll
    for (int k = 0; k < 4; ++k) {
        int idx = tid + k * 256;
        ((float4*)ws)[idx] = ((const float4*)W)[idx];
        ((float4*)us)[idx] = ((const float4*)(U + (size_t)i0 * 64))[idx];
    }
    __syncthreads();
    #pragma unroll
    for (int t = 0; t < 16; ++t) {
        int idx = t * 256 + tid;
        int il = idx >> 6, f = idx & 63;
        float sum = 0.f;
        #pragma unroll 8
        for (int e = 0; e < 64; ++e)
            sum += us[il * 64 + e] * ws[e * 64 + f];
        g_Mt[f * NT + i0 + il] = sum;
        g_Ut[f * NT + i0 + il] = us[il * 64 + f];
    }
}

// ---------- prep: V[i][b*64+d] = relu(prof-thr)*state ----------
__global__ void prep_v_kernel(const float* __restrict__ states,
                              const float* __restrict__ prof) {
    int idx4 = blockIdx.x * blockDim.x + threadIdx.x;  // [0, NT*32)
    int i  = idx4 >> 5;
    int q  = idx4 & 31;
    int c0 = q * 4;
    int b  = c0 >> 6;
    int d  = c0 & 63;
    float gg = fmaxf(prof[b * NT + i] - THRESH, 0.f);
    float4 st = *(const float4*)&states[((size_t)b * NT + i) * 64 + d];
    float4 o;
    o.x = st.x * gg; o.y = st.y * gg; o.z = st.z * gg; o.w = st.w * gg;
    *(float4*)&g_V[(size_t)i * 128 + c0] = o;
}

// ---------- fused main kernel ----------
// Block: 256 thr, j-tile = 64. smem: Ut tile (persist) | Mt tile | V tile | P tile
// S-phase: all 256 threads, 4x4 micro, scalar FFMA (LDS-bound either way).
// GEMM-phase: split-K, 2 groups x 128 thr, 8j x 8c micro, packed f32x2.
extern __shared__ float smem_dyn[];
__global__ void __launch_bounds__(256, 1)
dyadic_main_kernel(const float* __restrict__ states,
                   const float* __restrict__ bias_ptr,
                   float* __restrict__ out) {
    float* su = smem_dyn;            // 4096 floats: Ut tile [f][jl]
    float* sm = smem_dyn + 4096;     // 4096 floats: Mt tile [f][il]
    float* sv = smem_dyn + 8192;     // 8192 floats: V tile [il][c]
    float* sp = smem_dyn + 16384;    // 4096 floats: P tile [il][jl]

    const int tid = threadIdx.x;
    const int j0  = blockIdx.x * 64;
    const float bias = __ldg(bias_ptr);

    // persistent Ut tile load
    #pragma unroll
    for (int k = 0; k < 4; ++k) {
        int idx = tid + k * 256;
        int f = idx >> 4, q = idx & 15;
        *(float4*)&su[f * 64 + q * 4] =
            *(const float4*)&g_Ut[(size_t)f * NT + j0 + q * 4];
    }

    // S-phase mapping (4i x 4j per thread)
    const int ibS = (tid >> 4) * 4;
    const int jbS = (tid & 15) * 4;
    // GEMM mapping (split-K, 8j x 8c per thread)
    const int grp = tid >> 7;                 // 0/1: i halves
    const int jbG = ((tid & 127) >> 4) * 8;   // 0..56
    const int tx4 = (tid & 15) * 4;           // d-offset (both batches)

    unsigned long long acc[8][4];
    #pragma unroll
    for (int a = 0; a < 8; ++a)
        #pragma unroll
        for (int b = 0; b < 4; ++b) acc[a][b] = 0ULL;

    for (int t = 0; t < NT / 64; ++t) {
        const int i0 = t * 64;
        __syncthreads();  // previous phases done with sm/sv/sp

        // load Mt tile
        #pragma unroll
        for (int k = 0; k < 4; ++k) {
            int idx = tid + k * 256;
            int f = idx >> 4, q = idx & 15;
            *(float4*)&sm[f * 64 + q * 4] =
                *(const float4*)&g_Mt[(size_t)f * NT + i0 + q * 4];
        }
        // load V tile
        #pragma unroll
        for (int k = 0; k < 8; ++k) {
            int idx = tid + k * 256;
            int il = idx >> 5, q = idx & 31;
            *(float4*)&sv[il * 128 + q * 4] =
                *(const float4*)&g_V[(size_t)(i0 + il) * 128 + q * 4];
        }
        __syncthreads();

        // ---- S phase: S[i][j] = sum_f Mt[f][i] * Ut[f][j] ----
        float s00=0,s01=0,s02=0,s03=0, s10=0,s11=0,s12=0,s13=0;
        float s20=0,s21=0,s22=0,s23=0, s30=0,s31=0,s32=0,s33=0;
        #pragma unroll 8
        for (int e = 0; e < 64; ++e) {
            float4 mm = *(const float4*)&sm[e * 64 + ibS];
            float4 uu = *(const float4*)&su[e * 64 + jbS];
            s00 += mm.x * uu.x; s01 += mm.x * uu.y; s02 += mm.x * uu.z; s03 += mm.x * uu.w;
            s10 += mm.y * uu.x; s11 += mm.y * uu.y; s12 += mm.y * uu.z; s13 += mm.y * uu.w;
            s20 += mm.z * uu.x; s21 += mm.z * uu.y; s22 += mm.z * uu.z; s23 += mm.z * uu.w;
            s30 += mm.w * uu.x; s31 += mm.w * uu.y; s32 += mm.w * uu.z; s33 += mm.w * uu.w;
        }
        // sigmoid + diagonal mask, write P
        {
            float sr[4][4] = {{s00,s01,s02,s03},{s10,s11,s12,s13},
                              {s20,s21,s22,s23},{s30,s31,s32,s33}};
            #pragma unroll
            for (int r = 0; r < 4; ++r) {
                int gi = i0 + ibS + r;
                float4 pv;
                pv.x = (gi == j0 + jbS + 0) ? 0.f : sigmoidf_fast(sr[r][0] + bias);
                pv.y = (gi == j0 + jbS + 1) ? 0.f : sigmoidf_fast(sr[r][1] + bias);
                pv.z = (gi == j0 + jbS + 2) ? 0.f : sigmoidf_fast(sr[r][2] + bias);
                pv.w = (gi == j0 + jbS + 3) ? 0.f : sigmoidf_fast(sr[r][3] + bias);
                *(float4*)&sp[(ibS + r) * 64 + jbS] = pv;
            }
        }
        __syncthreads();

        // ---- GEMM phase: acc[j][c] += P[i][j] * V[i][c] (packed f32x2) ----
        #pragma unroll 2
        for (int ii = 0; ii < 32; ++ii) {
            const int i = (grp << 5) + ii;
            float4 pA = *(const float4*)&sp[i * 64 + jbG];
            float4 pB = *(const float4*)&sp[i * 64 + jbG + 4];
            ulonglong2 vA = *(const ulonglong2*)&sv[i * 128 + tx4];       // batch 0
            ulonglong2 vB = *(const ulonglong2*)&sv[i * 128 + 64 + tx4];  // batch 1
            unsigned long long pd[8];
            pd[0] = dup2(pA.x); pd[1] = dup2(pA.y); pd[2] = dup2(pA.z); pd[3] = dup2(pA.w);
            pd[4] = dup2(pB.x); pd[5] = dup2(pB.y); pd[6] = dup2(pB.z); pd[7] = dup2(pB.w);
            #pragma unroll
            for (int jj = 0; jj < 8; ++jj) {
                acc[jj][0] = ffma2(pd[jj], vA.x, acc[jj][0]);
                acc[jj][1] = ffma2(pd[jj], vA.y, acc[jj][1]);
                acc[jj][2] = ffma2(pd[jj], vB.x, acc[jj][2]);
                acc[jj][3] = ffma2(pd[jj], vB.y, acc[jj][3]);
            }
        }
    }

    // ---- epilogue: combine split-K partials, add state, store ----
    __syncthreads();
    if (grp == 1) {
        #pragma unroll
        for (int jj = 0; jj < 8; ++jj) {
            float* row = &sv[(jbG + jj) * 128];
            *(unsigned long long*)&row[tx4 + 0]      = acc[jj][0];
            *(unsigned long long*)&row[tx4 + 2]      = acc[jj][1];
            *(unsigned long long*)&row[64 + tx4 + 0] = acc[jj][2];
            *(unsigned long long*)&row[64 + tx4 + 2] = acc[jj][3];
        }
    }
    __syncthreads();
    if (grp == 0) {
        #pragma unroll
        for (int jj = 0; jj < 8; ++jj) {
            const int j = j0 + jbG + jj;
            const float* row = &sv[(jbG + jj) * 128];
            unsigned long long a0 = addf2(acc[jj][0], *(const unsigned long long*)&row[tx4 + 0]);
            unsigned long long a1 = addf2(acc[jj][1], *(const unsigned long long*)&row[tx4 + 2]);
            unsigned long long a2 = addf2(acc[jj][2], *(const unsigned long long*)&row[64 + tx4 + 0]);
            unsigned long long a3 = addf2(acc[jj][3], *(const unsigned long long*)&row[64 + tx4 + 2]);
            float r0 = __uint_as_float((unsigned)(a0 & 0xffffffffu));
            float r1 = __uint_as_float((unsigned)(a0 >> 32));
            float r2 = __uint_as_float((unsigned)(a1 & 0xffffffffu));
            float r3 = __uint_as_float((unsigned)(a1 >> 32));
            float r4 = __uint_as_float((unsigned)(a2 & 0xffffffffu));
            float r5 = __uint_as_float((unsigned)(a2 >> 32));
            float r6 = __uint_as_float((unsigned)(a3 & 0xffffffffu));
            float r7 = __uint_as_float((unsigned)(a3 >> 32));
            size_t base0 = ((size_t)j) * 64 + tx4;                   // batch 0
            size_t base1 = ((size_t)NT + j) * 64 + tx4;              // batch 1
            float4 st0 = *(const float4*)&states[base0];
            float4 st1 = *(const float4*)&states[base1];
            float4 o0 = make_float4(st0.x + r0, st0.y + r1, st0.z + r2, st0.w + r3);
            float4 o1 = make_float4(st1.x + r4, st1.y + r5, st1.z + r6, st1.w + r7);
            *(float4*)&out[base0] = o0;
            *(float4*)&out[base1] = o1;
        }
    }
}

extern "C" void kernel_launch(void* const* d_in, const int* in_sizes, int n_in,
                              void* d_out, int out_size) {
    const float* states = (const float*)d_in[0];  // [2, 8192, 64]
    const float* prof   = (const float*)d_in[1];  // [2, 8192]
    const float* U      = (const float*)d_in[2];  // [8192, 64]
    const float* W      = (const float*)d_in[3];  // [1, 64, 64]
    const float* bias   = (const float*)d_in[4];  // [1]
    float* out = (float*)d_out;

    cudaFuncSetAttribute(dyadic_main_kernel,
                         cudaFuncAttributeMaxDynamicSharedMemorySize, 80 * 1024);

    prep_mu_kernel<<<NT / 64, 256>>>(U, W);
    prep_v_kernel<<<(NT * 32) / 256, 256>>>(states, prof);
    dyadic_main_kernel<<<NT / 64, 256, 80 * 1024>>>(states, bias, out);
}

// round 7
// speedup vs baseline: 2.6034x; 2.6034x over previous
#include <cuda_runtime.h>
#include <cuda_bf16.h>
#include <cstdint>

#define NT 8192
#define THRESH 0.7f

// -------- global scratch (allocation-free rule) --------
__device__ __nv_bfloat16 g_Mhi[NT * 64];   // (U@W) split hi, [i][f]
__device__ __nv_bfloat16 g_Mlo[NT * 64];
__device__ __nv_bfloat16 g_Uhi[NT * 64];   // U split hi, [j][f]
__device__ __nv_bfloat16 g_Ulo[NT * 64];
__device__ __nv_bfloat16 g_Vthi[128 * NT]; // gated V^T split hi, [c=b*64+d][i]
__device__ __nv_bfloat16 g_Vtlo[128 * NT];

// -------- helpers --------
__device__ __forceinline__ uint32_t smem_u32(const void* p) {
    uint32_t a;
    asm("{ .reg .u64 t; cvta.to.shared.u64 t, %1; cvt.u32.u64 %0, t; }"
        : "=r"(a) : "l"(p));
    return a;
}
__device__ __forceinline__ void cpasync16(uint32_t saddr, const void* g) {
    asm volatile("cp.async.cg.shared.global [%0], [%1], 16;\n" :: "r"(saddr), "l"(g));
}
#define CP_COMMIT()  asm volatile("cp.async.commit_group;\n" ::: "memory")
#define CP_WAIT0()   asm volatile("cp.async.wait_group 0;\n" ::: "memory")

__device__ __forceinline__ void ldsm4(uint32_t* r, uint32_t a) {
    asm volatile("ldmatrix.sync.aligned.m8n8.x4.shared.b16 {%0,%1,%2,%3}, [%4];"
                 : "=r"(r[0]), "=r"(r[1]), "=r"(r[2]), "=r"(r[3]) : "r"(a));
}
__device__ __forceinline__ void mma_bf16(float* c, const uint32_t* a,
                                         uint32_t b0, uint32_t b1) {
    asm volatile("mma.sync.aligned.m16n8k16.row.col.f32.bf16.bf16.f32 "
                 "{%0,%1,%2,%3}, {%4,%5,%6,%7}, {%8,%9}, {%0,%1,%2,%3};"
                 : "+f"(c[0]), "+f"(c[1]), "+f"(c[2]), "+f"(c[3])
                 : "r"(a[0]), "r"(a[1]), "r"(a[2]), "r"(a[3]), "r"(b0), "r"(b1));
}
// pack two f32 -> bf16x2 (a -> upper half, b -> lower half)
__device__ __forceinline__ uint32_t packbf2(float a, float b) {
    uint32_t r;
    asm("cvt.rn.bf16x2.f32 %0, %1, %2;" : "=r"(r) : "f"(a), "f"(b));
    return r;
}
__device__ __forceinline__ float fast_sigmoid(float x) {  // x includes bias
    float e, r;
    asm("ex2.approx.f32 %0, %1;" : "=f"(e) : "f"(-1.44269504f * x));
    asm("rcp.approx.f32 %0, %1;" : "=f"(r) : "f"(1.0f + e));
    return r;
}
__device__ __forceinline__ void bf16split(float x, __nv_bfloat16& hi, __nv_bfloat16& lo) {
    hi = __float2bfloat16_rn(x);
    lo = __float2bfloat16_rn(x - __bfloat162float(hi));
}

// -------- SMEM layout (bytes) --------
#define OFF_UHI 0u
#define OFF_ULO 8192u
#define OFF_MHI 16384u
#define OFF_MLO 32768u
#define OFF_PHI 49152u
#define OFF_PLO 65536u
#define OFF_V0  81920u          // per buf: hi 32KB @+0, lo 32KB @+32768; 2 bufs
#define SMEM_TOTAL (81920u + 2u * 65536u)   // 212992

// ============ prep: M = U@W, bf16 splits of M and U ============
__global__ void prep_mu_kernel(const float* __restrict__ U,
                               const float* __restrict__ W) {
    __shared__ float ws[64 * 64];
    __shared__ float us[64 * 64];
    const int tid = threadIdx.x;
    const int i0  = blockIdx.x * 64;
    #pragma unroll
    for (int k = 0; k < 4; ++k) {
        int idx = tid + k * 256;
        ((float4*)ws)[idx] = ((const float4*)W)[idx];
        ((float4*)us)[idx] = ((const float4*)(U + (size_t)i0 * 64))[idx];
    }
    __syncthreads();
    #pragma unroll
    for (int t = 0; t < 16; ++t) {
        int idx = t * 256 + tid;
        int il = idx >> 6, f = idx & 63;
        float sum = 0.f;
        #pragma unroll 8
        for (int e = 0; e < 64; ++e)
            sum += us[il * 64 + e] * ws[e * 64 + f];
        __nv_bfloat16 hi, lo;
        bf16split(sum, hi, lo);
        size_t o = (size_t)(i0 + il) * 64 + f;
        g_Mhi[o] = hi; g_Mlo[o] = lo;
        bf16split(us[il * 64 + f], hi, lo);
        g_Uhi[o] = hi; g_Ulo[o] = lo;
    }
}

// ============ prep: V^T[c][i] = relu(prof-thr)*state, bf16 split ============
__global__ void prep_v_kernel(const float* __restrict__ states,
                              const float* __restrict__ prof) {
    __shared__ float sv[64 * 128];   // [il][c]
    const int tid = threadIdx.x;
    const int i0  = blockIdx.x * 64;
    #pragma unroll
    for (int k = 0; k < 8; ++k) {
        int idx = tid + k * 256;
        int il = idx >> 5, q = idx & 31;
        int c0 = q * 4, b = c0 >> 6, d = c0 & 63;
        float g = fmaxf(prof[b * NT + i0 + il] - THRESH, 0.f);
        float4 st = *(const float4*)&states[((size_t)b * NT + i0 + il) * 64 + d];
        float4 o; o.x = st.x * g; o.y = st.y * g; o.z = st.z * g; o.w = st.w * g;
        *(float4*)&sv[il * 128 + c0] = o;
    }
    __syncthreads();
    #pragma unroll
    for (int k = 0; k < 4; ++k) {
        int idx = tid + k * 256;
        int c = idx >> 3, ic = idx & 7;
        int ib = ic * 8;
        union { uint4 u; __nv_bfloat16 h[8]; } ph, pl;
        #pragma unroll
        for (int r = 0; r < 8; ++r) {
            __nv_bfloat16 hi, lo;
            bf16split(sv[(ib + r) * 128 + c], hi, lo);
            ph.h[r] = hi; pl.h[r] = lo;
        }
        size_t o = (size_t)c * NT + i0 + ib;
        *(uint4*)&g_Vthi[o] = ph.u;
        *(uint4*)&g_Vtlo[o] = pl.u;
    }
}

// ============ main fused kernel (warp HMMA) ============
extern __shared__ char smem[];
__global__ void __launch_bounds__(256, 1)
dyadic_hmma_kernel(const float* __restrict__ states,
                   const float* __restrict__ bias_ptr,
                   float* __restrict__ out) {
    const uint32_t sb = smem_u32(smem);
    const int tid = threadIdx.x;
    const int wid = tid >> 5;
    const int l   = tid & 31;
    const int j0  = blockIdx.x * 64;

    const int row16  = ((l >> 3) & 1) * 8 + (l & 7);  // row within m16 tile
    const int colsel = l >> 4;                        // 16B column select
    const int x7  = l & 7;                            // swizzle key (== row&7 everywhere)
    const int g   = l >> 2;                           // accum row group
    const int t4  = l & 3;                            // accum col group

    const int jb  = (wid & 3) * 16;   // phase A: j rows
    const int ibA = (wid >> 2) * 64;  // phase A: i half
    const int cb  = wid * 16;         // phase B: c rows

    // ---- persistent U tile (hi/lo), swizzled K-major [64 j][128B] ----
    #pragma unroll
    for (int k = 0; k < 2; ++k) {
        int q = tid + k * 256;                 // 512 chunks per half
        int r = q >> 3, c16 = q & 7;
        uint32_t d = (uint32_t)(r * 128 + ((c16 ^ (r & 7)) << 4));
        *(uint4*)(smem + OFF_UHI + d) = *(const uint4*)&g_Uhi[(size_t)(j0 + r) * 64 + c16 * 8];
        *(uint4*)(smem + OFF_ULO + d) = *(const uint4*)&g_Ulo[(size_t)(j0 + r) * 64 + c16 * 8];
    }

    // ---- prefetch helpers ----
    auto prefM = [&](int i0g) {
        #pragma unroll
        for (int k = 0; k < 4; ++k) {          // 1024 chunks per half
            int q = tid + k * 256;
            int r = q >> 3, c16 = q & 7;
            uint32_t d = (uint32_t)(r * 128 + ((c16 ^ (r & 7)) << 4));
            cpasync16(sb + OFF_MHI + d, &g_Mhi[(size_t)(i0g + r) * 64 + c16 * 8]);
            cpasync16(sb + OFF_MLO + d, &g_Mlo[(size_t)(i0g + r) * 64 + c16 * 8]);
        }
    };
    auto prefV = [&](int i0g, uint32_t vb) {
        #pragma unroll
        for (int k = 0; k < 8; ++k) {          // 2048 chunks per half
            int q = tid + k * 256;
            int c = q >> 4, c16 = q & 15;
            uint32_t d = (uint32_t)(c * 256 + ((c16 ^ (c & 7)) << 4));
            cpasync16(sb + vb + d,          &g_Vthi[(size_t)c * NT + i0g + c16 * 8]);
            cpasync16(sb + vb + 32768u + d, &g_Vtlo[(size_t)c * NT + i0g + c16 * 8]);
        }
    };

    prefM(0);
    prefV(0, OFF_V0);
    CP_COMMIT();

    const float bias = __ldg(bias_ptr);
    const int tdiag = j0 >> 7;
    const int dOff  = j0 & 127;

    // per-lane fixed smem row bases
    const uint32_t uAbase = sb + OFF_UHI + (uint32_t)(jb + row16) * 128;  // A phase A
    const uint32_t vAbase0 = (uint32_t)(cb + row16) * 256;                // A phase B (rel)

    float accB[8][4];
    #pragma unroll
    for (int a = 0; a < 8; ++a)
        #pragma unroll
        for (int b = 0; b < 4; ++b) accB[a][b] = 0.f;

    for (int t = 0; t < 64; ++t) {
        CP_WAIT0();
        __syncthreads();   // M(t), V(t) in smem; all warps done with previous phase B

        // ================= phase A: S^T[j][i] = U · M^T (3-term split) =================
        float accA[8][4];
        #pragma unroll
        for (int a = 0; a < 8; ++a)
            #pragma unroll
            for (int b = 0; b < 4; ++b) accA[a][b] = 0.f;

        #pragma unroll
        for (int kk = 0; kk < 4; ++kk) {
            uint32_t aoff = (uint32_t)(((kk * 2 + colsel) ^ x7) << 4);
            uint32_t aH[4], aL[4];
            ldsm4(aH, uAbase + aoff);
            ldsm4(aL, uAbase + 8192u + aoff);
            #pragma unroll
            for (int p = 0; p < 4; ++p) {
                uint32_t bbase = sb + OFF_MHI + (uint32_t)(ibA + p * 16 + row16) * 128 + aoff;
                uint32_t bH[4], bL[4];
                ldsm4(bH, bbase);
                ldsm4(bL, bbase + 16384u);
                // n-block 2p  : regs {0,2};  n-block 2p+1: regs {1,3}
                mma_bf16(accA[2 * p],     aH, bH[0], bH[2]);
                mma_bf16(accA[2 * p],     aH, bL[0], bL[2]);
                mma_bf16(accA[2 * p],     aL, bH[0], bH[2]);
                mma_bf16(accA[2 * p + 1], aH, bH[1], bH[3]);
                mma_bf16(accA[2 * p + 1], aH, bL[1], bL[3]);
                mma_bf16(accA[2 * p + 1], aL, bH[1], bH[3]);
            }
        }

        // ---- epilogue: sigmoid (+diag mask on 1 tile), split, store P^T ----
        {
            const bool dm = (t == tdiag);
            const int j1 = jb + g, j2 = j1 + 8;
            #pragma unroll
            for (int nb = 0; nb < 8; ++nb) {
                int i00 = ibA + nb * 8 + 2 * t4;       // i of value 0 (pair: i00, i00+1)
                float p00 = fast_sigmoid(accA[nb][0] + bias);
                float p01 = fast_sigmoid(accA[nb][1] + bias);
                float p10 = fast_sigmoid(accA[nb][2] + bias);
                float p11 = fast_sigmoid(accA[nb][3] + bias);
                if (dm) {
                    if (i00     == j1 + dOff) p00 = 0.f;
                    if (i00 + 1 == j1 + dOff) p01 = 0.f;
                    if (i00     == j2 + dOff) p10 = 0.f;
                    if (i00 + 1 == j2 + dOff) p11 = 0.f;
                }
                int c8 = i00 >> 3;                     // 16B column index
                uint32_t a1 = OFF_PHI + (uint32_t)(j1 * 256 + ((c8 ^ (j1 & 7)) << 4) + t4 * 4);
                uint32_t a2 = OFF_PHI + (uint32_t)(j2 * 256 + ((c8 ^ (j2 & 7)) << 4) + t4 * 4);
                uint32_t h1 = packbf2(p01, p00);       // upper = i+1, lower = i
                uint32_t h2 = packbf2(p11, p10);
                // residuals (lo = p - bf16(p))
                float r00 = p00 - __uint_as_float(h1 << 16);
                float r01 = p01 - __uint_as_float(h1 & 0xffff0000u);
                float r10 = p10 - __uint_as_float(h2 << 16);
                float r11 = p11 - __uint_as_float(h2 & 0xffff0000u);
                *(uint32_t*)(smem + a1)          = h1;
                *(uint32_t*)(smem + a2)          = h2;
                *(uint32_t*)(smem + a1 + 16384u) = packbf2(r01, r00);
                *(uint32_t*)(smem + a2 + 16384u) = packbf2(r11, r10);
            }
        }
        __syncthreads();   // P^T complete; all warps done reading sM

        if (t < 63) {
            prefM((t + 1) << 7);
            prefV((t + 1) << 7, OFF_V0 + (uint32_t)((t + 1) & 1) * 65536u);
            CP_COMMIT();
        }

        // ================= phase B: leaked^T[c][j] += V^T · P (3-term split) =================
        {
            const uint32_t vAbase = sb + OFF_V0 + (uint32_t)(t & 1) * 65536u + vAbase0;
            #pragma unroll
            for (int kk = 0; kk < 8; ++kk) {
                uint32_t aoff = (uint32_t)(((kk * 2 + colsel) ^ x7) << 4);
                uint32_t aH[4], aL[4];
                ldsm4(aH, vAbase + aoff);
                ldsm4(aL, vAbase + 32768u + aoff);
                #pragma unroll
                for (int p = 0; p < 4; ++p) {
                    uint32_t bbase = sb + OFF_PHI + (uint32_t)(p * 16 + row16) * 256 + aoff;
                    uint32_t bH[4], bL[4];
                    ldsm4(bH, bbase);
                    ldsm4(bL, bbase + 16384u);
                    mma_bf16(accB[2 * p],     aH, bH[0], bH[2]);
                    mma_bf16(accB[2 * p],     aH, bL[0], bL[2]);
                    mma_bf16(accB[2 * p],     aL, bH[0], bH[2]);
                    mma_bf16(accB[2 * p + 1], aH, bH[1], bH[3]);
                    mma_bf16(accB[2 * p + 1], aH, bL[1], bL[3]);
                    mma_bf16(accB[2 * p + 1], aL, bH[1], bH[3]);
                }
            }
        }
    }

    // ---- final epilogue: out = state + leaked ----
    {
        const int c1 = cb + g, c2 = c1 + 8;
        const int b1 = c1 >> 6, d1 = c1 & 63;
        const int b2 = c2 >> 6, d2 = c2 & 63;
        #pragma unroll
        for (int nb = 0; nb < 8; ++nb) {
            int j = j0 + nb * 8 + 2 * t4;
            size_t o1 = ((size_t)b1 * NT + j) * 64 + d1;
            size_t o2 = ((size_t)b2 * NT + j) * 64 + d2;
            out[o1]      = states[o1]      + accB[nb][0];
            out[o1 + 64] = states[o1 + 64] + accB[nb][1];
            out[o2]      = states[o2]      + accB[nb][2];
            out[o2 + 64] = states[o2 + 64] + accB[nb][3];
        }
    }
}

extern "C" void kernel_launch(void* const* d_in, const int* in_sizes, int n_in,
                              void* d_out, int out_size) {
    const float* states = (const float*)d_in[0];  // [2, 8192, 64]
    const float* prof   = (const float*)d_in[1];  // [2, 8192]
    const float* U      = (const float*)d_in[2];  // [8192, 64]
    const float* W      = (const float*)d_in[3];  // [1, 64, 64]
    const float* bias   = (const float*)d_in[4];  // [1]
    float* out = (float*)d_out;

    cudaFuncSetAttribute(dyadic_hmma_kernel,
                         cudaFuncAttributeMaxDynamicSharedMemorySize, SMEM_TOTAL);

    prep_mu_kernel<<<NT / 64, 256>>>(U, W);
    prep_v_kernel<<<NT / 64, 256>>>(states, prof);
    dyadic_hmma_kernel<<<NT / 64, 256, SMEM_TOTAL>>>(states, bias, out);
}

// round 8
// speedup vs baseline: 2.6717x; 1.0263x over previous
#include <cuda_runtime.h>
#include <cuda_bf16.h>
#include <cstdint>

#define NT 8192
#define THRESH 0.7f

// -------- global scratch (allocation-free rule) --------
__device__ __nv_bfloat16 g_Mhi[NT * 64];   // (U@W) split hi, [i][f]
__device__ __nv_bfloat16 g_Mlo[NT * 64];
__device__ __nv_bfloat16 g_Uhi[NT * 64];   // U split hi, [j][f]
__device__ __nv_bfloat16 g_Ulo[NT * 64];
__device__ __nv_bfloat16 g_Vthi[128 * NT]; // gated V^T split hi, [c=b*64+d][i]
__device__ __nv_bfloat16 g_Vtlo[128 * NT];

// -------- helpers --------
__device__ __forceinline__ uint32_t smem_u32(const void* p) {
    uint32_t a;
    asm("{ .reg .u64 t; cvta.to.shared.u64 t, %1; cvt.u32.u64 %0, t; }"
        : "=r"(a) : "l"(p));
    return a;
}
__device__ __forceinline__ void cpasync16(uint32_t saddr, const void* g) {
    asm volatile("cp.async.cg.shared.global [%0], [%1], 16;\n" :: "r"(saddr), "l"(g));
}
#define CP_COMMIT()  asm volatile("cp.async.commit_group;\n" ::: "memory")
#define CP_WAIT0()   asm volatile("cp.async.wait_group 0;\n" ::: "memory")
#define CP_WAIT1()   asm volatile("cp.async.wait_group 1;\n" ::: "memory")

__device__ __forceinline__ void ldsm4(uint32_t* r, uint32_t a) {
    asm volatile("ldmatrix.sync.aligned.m8n8.x4.shared.b16 {%0,%1,%2,%3}, [%4];"
                 : "=r"(r[0]), "=r"(r[1]), "=r"(r[2]), "=r"(r[3]) : "r"(a));
}
__device__ __forceinline__ void mma_bf16(float* c, const uint32_t* a,
                                         uint32_t b0, uint32_t b1) {
    asm volatile("mma.sync.aligned.m16n8k16.row.col.f32.bf16.bf16.f32 "
                 "{%0,%1,%2,%3}, {%4,%5,%6,%7}, {%8,%9}, {%0,%1,%2,%3};"
                 : "+f"(c[0]), "+f"(c[1]), "+f"(c[2]), "+f"(c[3])
                 : "r"(a[0]), "r"(a[1]), "r"(a[2]), "r"(a[3]), "r"(b0), "r"(b1));
}
__device__ __forceinline__ uint32_t packbf2(float a, float b) {
    uint32_t r;
    asm("cvt.rn.bf16x2.f32 %0, %1, %2;" : "=r"(r) : "f"(a), "f"(b));
    return r;
}
__device__ __forceinline__ float fast_sigmoid(float x) {
    float e, r;
    asm("ex2.approx.f32 %0, %1;" : "=f"(e) : "f"(-1.44269504f * x));
    asm("rcp.approx.f32 %0, %1;" : "=f"(r) : "f"(1.0f + e));
    return r;
}
__device__ __forceinline__ void bf16split(float x, __nv_bfloat16& hi, __nv_bfloat16& lo) {
    hi = __float2bfloat16_rn(x);
    lo = __float2bfloat16_rn(x - __bfloat162float(hi));
}

// -------- SMEM layout (bytes) --------
#define OFF_UHI 0u          //  8KB
#define OFF_ULO 8192u       //  8KB
#define OFF_M0  16384u      //  2 bufs x (hi 8KB + lo 8KB) = 32KB
#define OFF_PHI 49152u      //  8KB
#define OFF_PLO 57344u      //  8KB
#define OFF_V0  65536u      //  2 bufs x (hi 16KB + lo 16KB) = 64KB
#define SMEM_TOTAL 131072u  // 128KB

// ============ prep: M = U@W, bf16 splits of M and U (i-tile 32) ============
__global__ void prep_mu_kernel(const float* __restrict__ U,
                               const float* __restrict__ W) {
    __shared__ float ws[64 * 64];
    __shared__ float us[32 * 64];
    const int tid = threadIdx.x;
    const int i0  = blockIdx.x * 32;
    #pragma unroll
    for (int k = 0; k < 4; ++k)
        ((float4*)ws)[tid + k * 256] = ((const float4*)W)[tid + k * 256];
    #pragma unroll
    for (int k = 0; k < 2; ++k)
        ((float4*)us)[tid + k * 256] =
            ((const float4*)(U + (size_t)i0 * 64))[tid + k * 256];
    __syncthreads();
    #pragma unroll
    for (int t = 0; t < 8; ++t) {
        int idx = t * 256 + tid;
        int il = idx >> 6, f = idx & 63;
        float s0 = 0.f, s1 = 0.f, s2 = 0.f, s3 = 0.f;
        #pragma unroll
        for (int e = 0; e < 64; e += 4) {
            s0 += us[il * 64 + e]     * ws[e * 64 + f];
            s1 += us[il * 64 + e + 1] * ws[(e + 1) * 64 + f];
            s2 += us[il * 64 + e + 2] * ws[(e + 2) * 64 + f];
            s3 += us[il * 64 + e + 3] * ws[(e + 3) * 64 + f];
        }
        float sum = (s0 + s1) + (s2 + s3);
        __nv_bfloat16 hi, lo;
        bf16split(sum, hi, lo);
        size_t o = (size_t)(i0 + il) * 64 + f;
        g_Mhi[o] = hi; g_Mlo[o] = lo;
        bf16split(us[il * 64 + f], hi, lo);
        g_Uhi[o] = hi; g_Ulo[o] = lo;
    }
}

// ============ prep: V^T[c][i] = relu(prof-thr)*state, bf16 split (i-tile 32) ============
__global__ void prep_v_kernel(const float* __restrict__ states,
                              const float* __restrict__ prof) {
    __shared__ float sv[32 * 128];   // [il][c]
    const int tid = threadIdx.x;
    const int i0  = blockIdx.x * 32;
    #pragma unroll
    for (int k = 0; k < 4; ++k) {
        int idx = tid + k * 256;       // 1024 float4s
        int il = idx >> 5, q = idx & 31;
        int c0 = q * 4, b = c0 >> 6, d = c0 & 63;
        float g = fmaxf(prof[b * NT + i0 + il] - THRESH, 0.f);
        float4 st = *(const float4*)&states[((size_t)b * NT + i0 + il) * 64 + d];
        float4 o; o.x = st.x * g; o.y = st.y * g; o.z = st.z * g; o.w = st.w * g;
        *(float4*)&sv[il * 128 + c0] = o;
    }
    __syncthreads();
    #pragma unroll
    for (int k = 0; k < 2; ++k) {
        int idx = tid + k * 256;       // 512 chunks
        int c = idx >> 2, ic = idx & 3;
        int ib = ic * 8;
        union { uint4 u; __nv_bfloat16 h[8]; } ph, pl;
        #pragma unroll
        for (int r = 0; r < 8; ++r) {
            __nv_bfloat16 hi, lo;
            bf16split(sv[(ib + r) * 128 + c], hi, lo);
            ph.h[r] = hi; pl.h[r] = lo;
        }
        size_t o = (size_t)c * NT + i0 + ib;
        *(uint4*)&g_Vthi[o] = ph.u;
        *(uint4*)&g_Vtlo[o] = pl.u;
    }
}

// ---- one kk-step of phase A: accA += U-frag(kk) x M-frag(kk), 3 split terms ----
#define A_KK(ACC, MB, KK) do {                                                   \
    uint32_t _aoff = (uint32_t)((((KK) * 2 + colsel) ^ x7) << 4);                \
    uint32_t _aH[4], _aL[4];                                                     \
    ldsm4(_aH, uAbase + _aoff);                                                  \
    ldsm4(_aL, uAbase + 8192u + _aoff);                                          \
    _Pragma("unroll")                                                            \
    for (int _p = 0; _p < 2; ++_p) {                                             \
        uint32_t _bb = (MB) + (uint32_t)(ib2 + _p * 16 + row16) * 128 + _aoff;   \
        uint32_t _bH[4], _bL[4];                                                 \
        ldsm4(_bH, _bb);                                                         \
        ldsm4(_bL, _bb + 8192u);                                                 \
        mma_bf16(ACC[2 * _p],     _aH, _bH[0], _bH[2]);                          \
        mma_bf16(ACC[2 * _p],     _aH, _bL[0], _bL[2]);                          \
        mma_bf16(ACC[2 * _p],     _aL, _bH[0], _bH[2]);                          \
        mma_bf16(ACC[2 * _p + 1], _aH, _bH[1], _bH[3]);                          \
        mma_bf16(ACC[2 * _p + 1], _aH, _bL[1], _bL[3]);                          \
        mma_bf16(ACC[2 * _p + 1], _aL, _bH[1], _bH[3]);                          \
    }                                                                            \
} while (0)

// ---- epilogue quarter: 4 values of S -> sigmoid/mask -> P^T hi/lo stores ----
#define EPI_NB(ACC, NB, T) do {                                                  \
    int _i00 = ib2 + (NB) * 8 + 2 * t4;                                          \
    float _p00 = fast_sigmoid(ACC[NB][0] + bias);                                \
    float _p01 = fast_sigmoid(ACC[NB][1] + bias);                                \
    float _p10 = fast_sigmoid(ACC[NB][2] + bias);                                \
    float _p11 = fast_sigmoid(ACC[NB][3] + bias);                                \
    if ((T) == tdiag) {                                                          \
        if (_i00     == j1) _p00 = 0.f;                                          \
        if (_i00 + 1 == j1) _p01 = 0.f;                                          \
        if (_i00     == j2) _p10 = 0.f;                                          \
        if (_i00 + 1 == j2) _p11 = 0.f;                                          \
    }                                                                            \
    int _c8 = _i00 >> 3;                                                         \
    uint32_t _a1 = OFF_PHI + (uint32_t)(j1 * 128 + ((_c8 ^ (j1 & 7)) << 4) + t4 * 4); \
    uint32_t _a2 = OFF_PHI + (uint32_t)(j2 * 128 + ((_c8 ^ (j2 & 7)) << 4) + t4 * 4); \
    uint32_t _h1 = packbf2(_p01, _p00);                                          \
    uint32_t _h2 = packbf2(_p11, _p10);                                          \
    float _r00 = _p00 - __uint_as_float(_h1 << 16);                              \
    float _r01 = _p01 - __uint_as_float(_h1 & 0xffff0000u);                      \
    float _r10 = _p10 - __uint_as_float(_h2 << 16);                              \
    float _r11 = _p11 - __uint_as_float(_h2 & 0xffff0000u);                      \
    *(uint32_t*)(smem + _a1)         = _h1;                                      \
    *(uint32_t*)(smem + _a2)         = _h2;                                      \
    *(uint32_t*)(smem + _a1 + 8192u) = packbf2(_r01, _r00);                      \
    *(uint32_t*)(smem + _a2 + 8192u) = packbf2(_r11, _r10);                      \
} while (0)

// ---- full phase B: accB += V^T(t) x P(t), 3 split terms ----
#define PHASE_B(VB) do {                                                         \
    _Pragma("unroll")                                                            \
    for (int _kk = 0; _kk < 4; ++_kk) {                                          \
        uint32_t _aoff = (uint32_t)(((_kk * 2 + colsel) ^ x7) << 4);             \
        uint32_t _abase = (VB) + (uint32_t)(cb + row16) * 128 + _aoff;           \
        uint32_t _aH[4], _aL[4];                                                 \
        ldsm4(_aH, _abase);                                                      \
        ldsm4(_aL, _abase + 16384u);                                             \
        _Pragma("unroll")                                                        \
        for (int _p = 0; _p < 4; ++_p) {                                         \
            uint32_t _bb = sb + OFF_PHI + (uint32_t)(_p * 16 + row16) * 128 + _aoff; \
            uint32_t _bH[4], _bL[4];                                             \
            ldsm4(_bH, _bb);                                                     \
            ldsm4(_bL, _bb + 8192u);                                             \
            mma_bf16(accB[2 * _p],     _aH, _bH[0], _bH[2]);                     \
            mma_bf16(accB[2 * _p],     _aH, _bL[0], _bL[2]);                     \
            mma_bf16(accB[2 * _p],     _aL, _bH[0], _bH[2]);                     \
            mma_bf16(accB[2 * _p + 1], _aH, _bH[1], _bH[3]);                     \
            mma_bf16(accB[2 * _p + 1], _aH, _bL[1], _bL[3]);                     \
            mma_bf16(accB[2 * _p + 1], _aL, _bH[1], _bH[3]);                     \
        }                                                                        \
    }                                                                            \
} while (0)

// ---- one pipeline step: epilogue(T) interleaved with phase A(T+1), then B(T) ----
#define BODY(T, CUR, NXT) do {                                                   \
    CP_WAIT0();                                                                  \
    __syncthreads();                                                             \
    if ((T) + 1 < 128) {                                                         \
        prefV((T) + 1);                                                          \
        if ((T) + 2 < 128) prefM((T) + 2);                                       \
        CP_COMMIT();                                                             \
    }                                                                            \
    const uint32_t _mbN = sb + OFF_M0 + (uint32_t)((((T) + 1) & 1)) * 16384u;    \
    const bool _doA = ((T) + 1 < 128);                                           \
    if (_doA) {                                                                  \
        _Pragma("unroll")                                                        \
        for (int _z = 0; _z < 4; ++_z) {                                         \
            NXT[_z][0] = 0.f; NXT[_z][1] = 0.f; NXT[_z][2] = 0.f; NXT[_z][3] = 0.f; \
        }                                                                        \
        A_KK(NXT, _mbN, 0);                                                      \
    }                                                                            \
    EPI_NB(CUR, 0, T);                                                           \
    if (_doA) A_KK(NXT, _mbN, 1);                                                \
    EPI_NB(CUR, 1, T);                                                           \
    if (_doA) A_KK(NXT, _mbN, 2);                                                \
    EPI_NB(CUR, 2, T);                                                           \
    if (_doA) A_KK(NXT, _mbN, 3);                                                \
    EPI_NB(CUR, 3, T);                                                           \
    __syncthreads();                                                             \
    PHASE_B(sb + OFF_V0 + (uint32_t)(((T) & 1)) * 32768u);                       \
} while (0)

// ============ main fused kernel (HMMA, pipelined, i-tile 64) ============
extern __shared__ char smem[];
__global__ void __launch_bounds__(256, 1)
dyadic_hmma_kernel(const float* __restrict__ states,
                   const float* __restrict__ bias_ptr,
                   float* __restrict__ out) {
    const uint32_t sb = smem_u32(smem);
    const int tid = threadIdx.x;
    const int wid = tid >> 5;
    const int l   = tid & 31;
    const int j0  = blockIdx.x * 64;
    const int tdiag = blockIdx.x;

    const int row16  = ((l >> 3) & 1) * 8 + (l & 7);
    const int colsel = l >> 4;
    const int x7 = l & 7;
    const int g  = l >> 2;
    const int t4 = l & 3;

    const int jb  = (wid & 3) * 16;   // phase A: j rows
    const int ib2 = (wid >> 2) * 32;  // phase A: i cols
    const int cb  = wid * 16;         // phase B: c rows
    const int j1  = jb + g, j2 = j1 + 8;

    // ---- persistent U tile (plain loads) ----
    #pragma unroll
    for (int k = 0; k < 2; ++k) {
        int q = tid + k * 256;               // 512 chunks per half
        int r = q >> 3, c16 = q & 7;
        uint32_t d = (uint32_t)(r * 128 + ((c16 ^ (r & 7)) << 4));
        *(uint4*)(smem + OFF_UHI + d) = *(const uint4*)&g_Uhi[(size_t)(j0 + r) * 64 + c16 * 8];
        *(uint4*)(smem + OFF_ULO + d) = *(const uint4*)&g_Ulo[(size_t)(j0 + r) * 64 + c16 * 8];
    }

    auto prefM = [&](int tt) {               // M(tt) -> buf tt&1
        const uint32_t mb = sb + OFF_M0 + (uint32_t)(tt & 1) * 16384u;
        const size_t gi0 = (size_t)(tt << 6) * 64;
        #pragma unroll
        for (int k = 0; k < 2; ++k) {
            int q = tid + k * 256;           // 512 chunks per half
            int r = q >> 3, c16 = q & 7;
            uint32_t d = (uint32_t)(r * 128 + ((c16 ^ (r & 7)) << 4));
            cpasync16(mb + d,         &g_Mhi[gi0 + (size_t)r * 64 + c16 * 8]);
            cpasync16(mb + 8192u + d, &g_Mlo[gi0 + (size_t)r * 64 + c16 * 8]);
        }
    };
    auto prefV = [&](int tt) {               // V(tt) -> buf tt&1
        const uint32_t vb = sb + OFF_V0 + (uint32_t)(tt & 1) * 32768u;
        const int i0g = tt << 6;
        #pragma unroll
        for (int k = 0; k < 4; ++k) {
            int q = tid + k * 256;           // 1024 chunks per half
            int c = q >> 3, c16 = q & 7;
            uint32_t d = (uint32_t)(c * 128 + ((c16 ^ (c & 7)) << 4));
            cpasync16(vb + d,          &g_Vthi[(size_t)c * NT + i0g + c16 * 8]);
            cpasync16(vb + 16384u + d, &g_Vtlo[(size_t)c * NT + i0g + c16 * 8]);
        }
    };

    // prologue: M(0) | {V(0), M(1)}
    prefM(0);
    CP_COMMIT();
    prefV(0);
    prefM(1);
    CP_COMMIT();
    CP_WAIT1();          // M(0) ready
    __syncthreads();

    const float bias = __ldg(bias_ptr);
    const uint32_t uAbase = sb + OFF_UHI + (uint32_t)(jb + row16) * 128;

    float accB[8][4];
    #pragma unroll
    for (int a = 0; a < 8; ++a)
        #pragma unroll
        for (int b = 0; b < 4; ++b) accB[a][b] = 0.f;

    float accX[4][4], accY[4][4];
    // phase A(0) -> accX
    {
        #pragma unroll
        for (int z = 0; z < 4; ++z) {
            accX[z][0] = 0.f; accX[z][1] = 0.f; accX[z][2] = 0.f; accX[z][3] = 0.f;
        }
        const uint32_t mb0 = sb + OFF_M0;
        A_KK(accX, mb0, 0);
        A_KK(accX, mb0, 1);
        A_KK(accX, mb0, 2);
        A_KK(accX, mb0, 3);
    }

    for (int t = 0; t < 128; t += 2) {
        BODY(t, accX, accY);
        BODY(t + 1, accY, accX);
    }

    // ---- final epilogue: out = state + leaked ----
    {
        const int c1 = cb + g, c2 = c1 + 8;
        const int b1 = c1 >> 6, d1 = c1 & 63;
        const int b2 = c2 >> 6, d2 = c2 & 63;
        #pragma unroll
        for (int nb = 0; nb < 8; ++nb) {
            int j = j0 + nb * 8 + 2 * t4;
            size_t o1 = ((size_t)b1 * NT + j) * 64 + d1;
            size_t o2 = ((size_t)b2 * NT + j) * 64 + d2;
            out[o1]      = states[o1]      + accB[nb][0];
            out[o1 + 64] = states[o1 + 64] + accB[nb][1];
            out[o2]      = states[o2]      + accB[nb][2];
            out[o2 + 64] = states[o2 + 64] + accB[nb][3];
        }
    }
}

extern "C" void kernel_launch(void* const* d_in, const int* in_sizes, int n_in,
                              void* d_out, int out_size) {
    const float* states = (const float*)d_in[0];  // [2, 8192, 64]
    const float* prof   = (const float*)d_in[1];  // [2, 8192]
    const float* U      = (const float*)d_in[2];  // [8192, 64]
    const float* W      = (const float*)d_in[3];  // [1, 64, 64]
    const float* bias   = (const float*)d_in[4];  // [1]
    float* out = (float*)d_out;

    cudaFuncSetAttribute(dyadic_hmma_kernel,
                         cudaFuncAttributeMaxDynamicSharedMemorySize, SMEM_TOTAL);

    prep_mu_kernel<<<NT / 32, 256>>>(U, W);
    prep_v_kernel<<<NT / 32, 256>>>(states, prof);
    dyadic_hmma_kernel<<<NT / 64, 256, SMEM_TOTAL>>>(states, bias, out);
}